// round 13
// baseline (speedup 1.0000x reference)
#include <cuda_runtime.h>
#include <math.h>

// ---------------- geometry ----------------
#define W_    2048
#define HOUT  2046                 // VALID 3x3 output dim
#define NTOT  (W_ * W_)

// warp-strip decomposition: thread = 2 cols (float2), warp = 64 input cols,
// 62 owned output cols. Strip 32 ends exactly at col 2048 -> no col clipping.
// BAND-MAJOR warp mapping (R12 win): warps of one block cover ADJACENT strips
// of the SAME row band -> contiguous instantaneous footprint.
#define COLS_OUT 62
#define R_OUT  30
#define STRIPS 33                  // 33*62 = 2046 exactly
#define BANDS  69                  // ceil(2046/30)
#define NWARPS (STRIPS * BANDS)    // 2277
#define WPB    8                   // warps per block (256 threads)
#define NBLOCKS ((NWARPS + WPB - 1) / WPB)  // 285

__device__ float g_bpart[3 * NBLOCKS];
__device__ unsigned int g_count;   // zero at module load; reset by last block

// per-row derived state: horizontal 3-sums and horizontal differences
struct RowState {
    float hE0, hE1;     // 3-sum of E centered at c0 / c0+1
    float hXX0, hXX1;   // 3-sum of sxx
    float hXY0, hXY1;   // 3-sum of sxy
    float dXY0, dXY1;   // sxy(j-1) - sxy(j+1)
    float dYY0, dYY1;   // syy(j-1) - syy(j+1)
};

__device__ __forceinline__ float warp_sum(float x) {
#pragma unroll
    for (int o = 16; o > 0; o >>= 1) x += __shfl_down_sync(0xffffffffu, x, o);
    return x;
}

__global__ __launch_bounds__(256, 3)
void stress_loss_kernel(const float* __restrict__ pE,
                        const float* __restrict__ pv,
                        const float* __restrict__ ps,
                        float* __restrict__ out)
{
    const int wl   = threadIdx.x >> 5;
    const int w    = blockIdx.x * WPB + wl;
    const int lane = threadIdx.x & 31;
    const int tid  = threadIdx.x;
    float accx = 0.f, accy = 0.f, accE = 0.f;

    if (w < NWARPS) {
        // ---- band-major mapping ----
        const int band  = w / STRIPS;
        const int strip = w - band * STRIPS;
        const int cb = strip * COLS_OUT;
        const int r0 = band * R_OUT;
        const int rows_out = min(R_OUT, HOUT - r0);
        const int c0 = cb + lane * 2;
        const int own_hi_c = (strip == STRIPS - 1) ? W_ : cb + COLS_OUT;
        const int own_hi_r = (band  == BANDS  - 1) ? W_ : r0 + R_OUT;
        const bool ownc0 = (c0     < own_hi_c);
        const bool ownc1 = (c0 + 1 < own_hi_c);
        const bool ok0 = (lane > 0);    // output p = 2*lane   valid iff >=1
        const bool ok1 = (lane < 31);   // output p = 2*lane+1 valid iff <63

        RowState A, B, C;

        auto do_row = [&](int r, RowState& o, bool ownrow) {
            const int base = r * W_ + c0;            // c0 even -> aligned float2
            const float2 E2  = *reinterpret_cast<const float2*>(pE + base);
            const float2 v2  = *reinterpret_cast<const float2*>(pv + base);
            const float2 s01 = *reinterpret_cast<const float2*>(ps + 3 * base);
            const float2 s23 = *reinterpret_cast<const float2*>(ps + 3 * base + 2);
            const float2 s45 = *reinterpret_cast<const float2*>(ps + 3 * base + 4);

            const float E0 = E2.x,  E1 = E2.y;
            const float v0 = v2.x,  v1 = v2.y;
            const float e00 = s01.x, e10 = s01.y, e20 = s23.x;
            const float e01 = s23.y, e11 = s45.x, e21 = s45.y;

            const float f0 = __fdividef(E0, 1.0f - v0 * v0);
            const float f1 = __fdividef(E1, 1.0f - v1 * v1);
            const float xx0 = (e00 + v0 * e10) * f0;
            const float xx1 = (e01 + v1 * e11) * f1;
            const float yy0 = (v0 * e00 + e10) * f0;
            const float yy1 = (v1 * e01 + e11) * f1;
            const float xy0 = e20 * (1.0f - v0) * 0.5f * f0;
            const float xy1 = e21 * (1.0f - v1) * 0.5f * f1;

            // 8 shuffles/row; lane-edge garbage feeds only excluded outputs
            const float El = __shfl_up_sync  (0xffffffffu, E1,  1);
            const float Er = __shfl_down_sync(0xffffffffu, E0,  1);
            const float xl = __shfl_up_sync  (0xffffffffu, xx1, 1);
            const float xr = __shfl_down_sync(0xffffffffu, xx0, 1);
            const float yl = __shfl_up_sync  (0xffffffffu, xy1, 1);
            const float yr = __shfl_down_sync(0xffffffffu, xy0, 1);
            const float sl = __shfl_up_sync  (0xffffffffu, yy1, 1);
            const float sr = __shfl_down_sync(0xffffffffu, yy0, 1);

            o.hE0  = El + E0 + E1;   o.hE1  = E0 + E1 + Er;
            o.hXX0 = xl + xx0 + xx1; o.hXX1 = xx0 + xx1 + xr;
            o.hXY0 = yl + xy0 + xy1; o.hXY1 = xy0 + xy1 + yr;
            o.dXY0 = yl - xy1;       o.dXY1 = xy0 - yr;
            o.dYY0 = sl - yy1;       o.dYY1 = yy0 - sr;

            if (ownrow) {
                if (ownc0) accE += E0;
                if (ownc1) accE += E1;
            }
        };

        do_row(r0,     A, (r0     < own_hi_r));
        do_row(r0 + 1, B, (r0 + 1 < own_hi_r));

#pragma unroll 6
        for (int i = 0; i < rows_out; i++) {
            const int r = r0 + i + 2;
            do_row(r, C, (r < own_hi_r));

            if (ok0) {
                const float Ec = A.hE0 + B.hE0 + C.hE0;
                const float fx = C.hXX0 - A.hXX0 + (A.dXY0 + B.dXY0 + C.dXY0);
                const float fy = (A.dYY0 + B.dYY0 + C.dYY0) + C.hXY0 - A.hXY0;
                const float inv = __fdividef(1.0f, Ec);
                accx += fabsf(fx * inv);
                accy += fabsf(fy * inv);
            }
            if (ok1) {
                const float Ec = A.hE1 + B.hE1 + C.hE1;
                const float fx = C.hXX1 - A.hXX1 + (A.dXY1 + B.dXY1 + C.dXY1);
                const float fy = (A.dYY1 + B.dYY1 + C.dYY1) + C.hXY1 - A.hXY1;
                const float inv = __fdividef(1.0f, Ec);
                accx += fabsf(fx * inv);
                accy += fabsf(fy * inv);
            }
            A = B; B = C;
        }
    }

    // ---- block reduction ----
    accx = warp_sum(accx);
    accy = warp_sum(accy);
    accE = warp_sum(accE);

    __shared__ float red[3][WPB];
    __shared__ int isLast;
    if (lane == 0) {
        red[0][wl] = accx;
        red[1][wl] = accy;
        red[2][wl] = accE;
    }
    __syncthreads();
    if (tid == 0) {
        float ax = 0.f, ay = 0.f, ae = 0.f;
#pragma unroll
        for (int q = 0; q < WPB; q++) { ax += red[0][q]; ay += red[1][q]; ae += red[2][q]; }
        g_bpart[blockIdx.x]               = ax;
        g_bpart[NBLOCKS + blockIdx.x]     = ay;
        g_bpart[2 * NBLOCKS + blockIdx.x] = ae;
        __threadfence();
        const unsigned int old = atomicAdd(&g_count, 1u);
        isLast = (old == NBLOCKS - 1);
    }
    __syncthreads();

    // ---- last block finalizes (fixed-order sum -> deterministic) ----
    if (isLast) {
        volatile const float* vp = (volatile const float*)g_bpart;
        double ax = 0.0, ay = 0.0, ae = 0.0;
        for (int i = tid; i < NBLOCKS; i += 256) {
            ax += (double)vp[i];
            ay += (double)vp[NBLOCKS + i];
            ae += (double)vp[2 * NBLOCKS + i];
        }
        __shared__ double sax[256], say[256], sae[256];
        sax[tid] = ax; say[tid] = ay; sae[tid] = ae;
        __syncthreads();
        for (int s = 128; s > 0; s >>= 1) {
            if (tid < s) { sax[tid] += sax[tid + s]; say[tid] += say[tid + s]; sae[tid] += sae[tid + s]; }
            __syncthreads();
        }
        if (tid == 0) {
            const double M = (double)HOUT * (double)HOUT;
            out[0] = (float)(sax[0] / M + say[0] / M
                             + fabs(sae[0] / (double)NTOT - 1.0) / 100.0);
            g_count = 0;   // reset for next graph replay
        }
    }
}

extern "C" void kernel_launch(void* const* d_in, const int* in_sizes, int n_in,
                              void* d_out, int out_size)
{
    const float* pred_E = (const float*)d_in[0];
    const float* pred_v = (const float*)d_in[1];
    const float* strain = (const float*)d_in[2];
    float* out = (float*)d_out;

    stress_loss_kernel<<<NBLOCKS, 256>>>(pred_E, pred_v, strain, out);
}

// round 14
// speedup vs baseline: 1.0793x; 1.0793x over previous
#include <cuda_runtime.h>
#include <math.h>

// ---------------- geometry ----------------
#define W_    2048
#define HOUT  2046                 // VALID 3x3 output dim
#define NTOT  (W_ * W_)

// warp-strip decomposition: thread = 2 cols (float2), warp = 64 input cols,
// 62 owned output cols. Strip 32 ends exactly at col 2048 -> no col clipping.
// BAND-MAJOR warp mapping (R12 win): warps of one block cover ADJACENT strips
// of the SAME row band -> contiguous instantaneous footprint.
// NEW (R14): prefetch.global.L1 two rows ahead -- lookahead with ZERO register
// cost, converting per-row L2-hit latency (~240cyc) into L1 hits (~32cyc).
#define COLS_OUT 62
#define R_OUT  20
#define STRIPS 33                  // 33*62 = 2046 exactly
#define BANDS  103                 // ceil(2046/20)
#define NWARPS (STRIPS * BANDS)    // 3399
#define WPB    8                   // warps per block (256 threads)
#define NBLOCKS ((NWARPS + WPB - 1) / WPB)  // 425

#define PF_ROWS 2                  // prefetch distance (rows)

__device__ float g_bpart[3 * NBLOCKS];
__device__ unsigned int g_count;   // zero at module load; reset by last block

// per-row derived state: horizontal 3-sums and horizontal differences
struct RowState {
    float hE0, hE1;     // 3-sum of E centered at c0 / c0+1
    float hXX0, hXX1;   // 3-sum of sxx
    float hXY0, hXY1;   // 3-sum of sxy
    float dXY0, dXY1;   // sxy(j-1) - sxy(j+1)
    float dYY0, dYY1;   // syy(j-1) - syy(j+1)
};

__device__ __forceinline__ float warp_sum(float x) {
#pragma unroll
    for (int o = 16; o > 0; o >>= 1) x += __shfl_down_sync(0xffffffffu, x, o);
    return x;
}

__global__ __launch_bounds__(256, 3)
void stress_loss_kernel(const float* __restrict__ pE,
                        const float* __restrict__ pv,
                        const float* __restrict__ ps,
                        float* __restrict__ out)
{
    const int wl   = threadIdx.x >> 5;
    const int w    = blockIdx.x * WPB + wl;
    const int lane = threadIdx.x & 31;
    const int tid  = threadIdx.x;
    float accx = 0.f, accy = 0.f, accE = 0.f;

    if (w < NWARPS) {
        // ---- band-major mapping ----
        const int band  = w / STRIPS;
        const int strip = w - band * STRIPS;
        const int cb = strip * COLS_OUT;
        const int r0 = band * R_OUT;
        const int rows_out = min(R_OUT, HOUT - r0);
        const int c0 = cb + lane * 2;
        const int own_hi_c = (strip == STRIPS - 1) ? W_ : cb + COLS_OUT;
        const int own_hi_r = (band  == BANDS  - 1) ? W_ : r0 + R_OUT;
        const bool ownc0 = (c0     < own_hi_c);
        const bool ownc1 = (c0 + 1 < own_hi_c);
        const bool ok0 = (lane > 0);    // output p = 2*lane   valid iff >=1
        const bool ok1 = (lane < 31);   // output p = 2*lane+1 valid iff <63

        RowState A, B, C;

        auto do_row = [&](int r, RowState& o, bool ownrow) {
            const int base = r * W_ + c0;            // c0 even -> aligned float2
            const float2 E2  = *reinterpret_cast<const float2*>(pE + base);
            const float2 v2  = *reinterpret_cast<const float2*>(pv + base);
            const float2 s01 = *reinterpret_cast<const float2*>(ps + 3 * base);
            const float2 s23 = *reinterpret_cast<const float2*>(ps + 3 * base + 2);
            const float2 s45 = *reinterpret_cast<const float2*>(ps + 3 * base + 4);

            // ---- L1 prefetch PF_ROWS ahead (no reg writeback, no scoreboard)
            // one prefetch per stream suffices: per-warp lane starts touch
            // every 128B line of each stream's row span.
            {
                const int rpf  = min(r + PF_ROWS, W_ - 1);
                const int bpf  = rpf * W_ + c0;
                asm volatile("prefetch.global.L1 [%0];" :: "l"(pE + bpf));
                asm volatile("prefetch.global.L1 [%0];" :: "l"(pv + bpf));
                asm volatile("prefetch.global.L1 [%0];" :: "l"(ps + 3 * bpf));
            }

            const float E0 = E2.x,  E1 = E2.y;
            const float v0 = v2.x,  v1 = v2.y;
            const float e00 = s01.x, e10 = s01.y, e20 = s23.x;
            const float e01 = s23.y, e11 = s45.x, e21 = s45.y;

            const float f0 = __fdividef(E0, 1.0f - v0 * v0);
            const float f1 = __fdividef(E1, 1.0f - v1 * v1);
            const float xx0 = (e00 + v0 * e10) * f0;
            const float xx1 = (e01 + v1 * e11) * f1;
            const float yy0 = (v0 * e00 + e10) * f0;
            const float yy1 = (v1 * e01 + e11) * f1;
            const float xy0 = e20 * (1.0f - v0) * 0.5f * f0;
            const float xy1 = e21 * (1.0f - v1) * 0.5f * f1;

            // 8 shuffles/row; lane-edge garbage feeds only excluded outputs
            const float El = __shfl_up_sync  (0xffffffffu, E1,  1);
            const float Er = __shfl_down_sync(0xffffffffu, E0,  1);
            const float xl = __shfl_up_sync  (0xffffffffu, xx1, 1);
            const float xr = __shfl_down_sync(0xffffffffu, xx0, 1);
            const float yl = __shfl_up_sync  (0xffffffffu, xy1, 1);
            const float yr = __shfl_down_sync(0xffffffffu, xy0, 1);
            const float sl = __shfl_up_sync  (0xffffffffu, yy1, 1);
            const float sr = __shfl_down_sync(0xffffffffu, yy0, 1);

            o.hE0  = El + E0 + E1;   o.hE1  = E0 + E1 + Er;
            o.hXX0 = xl + xx0 + xx1; o.hXX1 = xx0 + xx1 + xr;
            o.hXY0 = yl + xy0 + xy1; o.hXY1 = xy0 + xy1 + yr;
            o.dXY0 = yl - xy1;       o.dXY1 = xy0 - yr;
            o.dYY0 = sl - yy1;       o.dYY1 = yy0 - sr;

            if (ownrow) {
                if (ownc0) accE += E0;
                if (ownc1) accE += E1;
            }
        };

        do_row(r0,     A, (r0     < own_hi_r));
        do_row(r0 + 1, B, (r0 + 1 < own_hi_r));

#pragma unroll 4
        for (int i = 0; i < rows_out; i++) {
            const int r = r0 + i + 2;
            do_row(r, C, (r < own_hi_r));

            if (ok0) {
                const float Ec = A.hE0 + B.hE0 + C.hE0;
                const float fx = C.hXX0 - A.hXX0 + (A.dXY0 + B.dXY0 + C.dXY0);
                const float fy = (A.dYY0 + B.dYY0 + C.dYY0) + C.hXY0 - A.hXY0;
                const float inv = __fdividef(1.0f, Ec);
                accx += fabsf(fx * inv);
                accy += fabsf(fy * inv);
            }
            if (ok1) {
                const float Ec = A.hE1 + B.hE1 + C.hE1;
                const float fx = C.hXX1 - A.hXX1 + (A.dXY1 + B.dXY1 + C.dXY1);
                const float fy = (A.dYY1 + B.dYY1 + C.dYY1) + C.hXY1 - A.hXY1;
                const float inv = __fdividef(1.0f, Ec);
                accx += fabsf(fx * inv);
                accy += fabsf(fy * inv);
            }
            A = B; B = C;
        }
    }

    // ---- block reduction ----
    accx = warp_sum(accx);
    accy = warp_sum(accy);
    accE = warp_sum(accE);

    __shared__ float red[3][WPB];
    __shared__ int isLast;
    if (lane == 0) {
        red[0][wl] = accx;
        red[1][wl] = accy;
        red[2][wl] = accE;
    }
    __syncthreads();
    if (tid == 0) {
        float ax = 0.f, ay = 0.f, ae = 0.f;
#pragma unroll
        for (int q = 0; q < WPB; q++) { ax += red[0][q]; ay += red[1][q]; ae += red[2][q]; }
        g_bpart[blockIdx.x]               = ax;
        g_bpart[NBLOCKS + blockIdx.x]     = ay;
        g_bpart[2 * NBLOCKS + blockIdx.x] = ae;
        __threadfence();
        const unsigned int old = atomicAdd(&g_count, 1u);
        isLast = (old == NBLOCKS - 1);
    }
    __syncthreads();

    // ---- last block finalizes (fixed-order sum -> deterministic) ----
    if (isLast) {
        volatile const float* vp = (volatile const float*)g_bpart;
        double ax = 0.0, ay = 0.0, ae = 0.0;
        for (int i = tid; i < NBLOCKS; i += 256) {
            ax += (double)vp[i];
            ay += (double)vp[NBLOCKS + i];
            ae += (double)vp[2 * NBLOCKS + i];
        }
        __shared__ double sax[256], say[256], sae[256];
        sax[tid] = ax; say[tid] = ay; sae[tid] = ae;
        __syncthreads();
        for (int s = 128; s > 0; s >>= 1) {
            if (tid < s) { sax[tid] += sax[tid + s]; say[tid] += say[tid + s]; sae[tid] += sae[tid + s]; }
            __syncthreads();
        }
        if (tid == 0) {
            const double M = (double)HOUT * (double)HOUT;
            out[0] = (float)(sax[0] / M + say[0] / M
                             + fabs(sae[0] / (double)NTOT - 1.0) / 100.0);
            g_count = 0;   // reset for next graph replay
        }
    }
}

extern "C" void kernel_launch(void* const* d_in, const int* in_sizes, int n_in,
                              void* d_out, int out_size)
{
    const float* pred_E = (const float*)d_in[0];
    const float* pred_v = (const float*)d_in[1];
    const float* strain = (const float*)d_in[2];
    float* out = (float*)d_out;

    stress_loss_kernel<<<NBLOCKS, 256>>>(pred_E, pred_v, strain, out);
}